// round 12
// baseline (speedup 1.0000x reference)
#include <cuda_runtime.h>
#include <cuda_bf16.h>
#include <cuda_fp16.h>
#include <cstdint>

#define BB 4
#define SS 2048
#define DD 1024
#define HH 16
#define HD 64
#define MROWS (BB*SS)   // 8192
#define QSCALE 0.18033688011112042f   // 0.125 * log2(e)

// ------------------------- device scratch ----------------------------------
__device__ __half g_xh [MROWS*DD];
__device__ __half g_qh [MROWS*DD];
__device__ __half g_kh [MROWS*DD];
__device__ __half g_vh [MROWS*DD];
__device__ __half g_ch [MROWS*DD];
__device__ __half g_wt16[3*DD*DD];          // Wq^T | Wk^T | Wv^T fp16
__device__ __half g_wohi[DD*DD];
__device__ __half g_wolo[DD*DD];
__device__ uint32_t g_mbits[BB*SS*(SS/32)];

// ------------------------- helpers -----------------------------------------
__device__ __forceinline__ uint32_t smem_u32(const void* p) {
    uint32_t a;
    asm("{ .reg .u64 t; cvta.to.shared.u64 t, %1; cvt.u32.u64 %0, t; }"
        : "=r"(a) : "l"(p));
    return a;
}
__device__ __forceinline__ float fast_exp2(float x) {
    float r;
    asm("ex2.approx.ftz.f32 %0, %1;" : "=f"(r) : "f"(x));
    return r;
}
__device__ __forceinline__ uint32_t pack_f16(float lo, float hi) {
    uint32_t r;
    asm("cvt.rn.f16x2.f32 %0, %1, %2;" : "=r"(r) : "f"(hi), "f"(lo));
    return r;
}
__device__ __forceinline__ void mma16816h(float* d, const uint32_t* a,
                                          const uint32_t* b) {
    asm volatile(
        "mma.sync.aligned.m16n8k16.row.col.f32.f16.f16.f32 "
        "{%0,%1,%2,%3}, {%4,%5,%6,%7}, {%8,%9}, {%0,%1,%2,%3};"
        : "+f"(d[0]), "+f"(d[1]), "+f"(d[2]), "+f"(d[3])
        : "r"(a[0]), "r"(a[1]), "r"(a[2]), "r"(a[3]), "r"(b[0]), "r"(b[1]));
}
__device__ __forceinline__ void ldsm4(uint32_t* r, uint32_t addr) {
    asm volatile("ldmatrix.sync.aligned.m8n8.x4.shared.b16 {%0,%1,%2,%3}, [%4];"
                 : "=r"(r[0]), "=r"(r[1]), "=r"(r[2]), "=r"(r[3]) : "r"(addr));
}
__device__ __forceinline__ void ldsm4t(uint32_t* r, uint32_t addr) {
    asm volatile("ldmatrix.sync.aligned.m8n8.x4.trans.shared.b16 {%0,%1,%2,%3}, [%4];"
                 : "=r"(r[0]), "=r"(r[1]), "=r"(r[2]), "=r"(r[3]) : "r"(addr));
}
__device__ __forceinline__ void cpasync16(uint32_t saddr, const void* gaddr) {
    asm volatile("cp.async.cg.shared.global [%0], [%1], 16;"
                 :: "r"(saddr), "l"(gaddr));
}
#define CP_COMMIT() asm volatile("cp.async.commit_group;" ::: "memory")
#define CP_WAIT0()  asm volatile("cp.async.wait_group 0;" ::: "memory")
#define CP_WAIT1()  asm volatile("cp.async.wait_group 1;" ::: "memory")

// ---------------------------------------------------------------------------
// prep: tofp16(x) + transpose16(Wq,Wk,Wv) in one launch
// ---------------------------------------------------------------------------
__global__ void __launch_bounds__(256) prep_kernel(
    const float4* __restrict__ x4, __half* __restrict__ xh,
    const float* __restrict__ W0, const float* __restrict__ W1,
    const float* __restrict__ W2, __half* __restrict__ T) {
    const int b = blockIdx.x;
    const int tid = threadIdx.x;
    if (b < 512) {
        const int n4 = MROWS * DD / 4;
        for (int i = b * 256 + tid; i < n4; i += 512 * 256) {
            float4 v = x4[i];
            uint2 o;
            o.x = pack_f16(v.x, v.y);
            o.y = pack_f16(v.z, v.w);
            *(uint2*)(xh + 4 * (size_t)i) = o;
        }
    } else {
        __shared__ float tile[32 * 33];
        const int t = b - 512;              // 0..3071
        const int z = t >> 10, rem = t & 1023;
        const float* W = (z == 0) ? W0 : (z == 1) ? W1 : W2;
        __half* Tz = T + (size_t)z * DD * DD;
        const int n0 = (rem & 31) * 32, k0 = (rem >> 5) * 32;
        const int tx = tid & 31, j0 = tid >> 5;
        for (int j = j0; j < 32; j += 8)
            tile[j * 33 + tx] = W[(size_t)(k0 + j) * DD + n0 + tx];
        __syncthreads();
        for (int j = j0; j < 32; j += 8)
            Tz[(size_t)(n0 + j) * DD + k0 + tx] = __float2half(tile[tx * 33 + j]);
    }
}

// ---------------------------------------------------------------------------
// fused QKV GEMM (fp32-acc) + mask_pack aux CTAs. (unchanged from R11)
// ---------------------------------------------------------------------------
#define G16_A   0
#define G16_B   10240
#define G16_STG 20480
#define G16_SMEM (3*G16_STG)

__global__ void __launch_bounds__(256, 2) hmma_qkv_kernel(
    const __half* __restrict__ Ah, const __half* __restrict__ Bh,
    const float* __restrict__ bq, const float* __restrict__ bk,
    const float* __restrict__ bv,
    __half* __restrict__ Qo, __half* __restrict__ Ko, __half* __restrict__ Vo,
    const int* __restrict__ Mask, uint32_t* __restrict__ Mbits) {
    extern __shared__ char dsm[];
    const int tid  = threadIdx.x;
    const int lane = tid & 31;
    const int wid  = tid >> 5;

    // ---- aux: mask pack ----
    if (blockIdx.x == 24) {
        const int wbase = blockIdx.y * 8192 + wid * 1024;
        for (int it = 0; it < 64; it++) {
            const int w0 = wbase + it * 16;
            int vv[16];
#pragma unroll
            for (int j = 0; j < 16; j++)
                vv[j] = Mask[(size_t)(w0 + j) * 32 + lane];
            uint32_t bb[16];
#pragma unroll
            for (int j = 0; j < 16; j++)
                bb[j] = __ballot_sync(0xffffffff, vv[j] != 0);
            if (lane < 4)
                *(uint4*)(Mbits + w0 + lane * 4) =
                    make_uint4(bb[lane * 4], bb[lane * 4 + 1],
                               bb[lane * 4 + 2], bb[lane * 4 + 3]);
        }
        return;
    }

    const uint32_t su = smem_u32(dsm);
    const int wm   = wid & 3;
    const int wn   = wid >> 2;
    const int m0   = blockIdx.y * 128;
    const int n0g  = blockIdx.x * 128;
    const int seg  = n0g >> 10;
    const int n0   = n0g & 1023;
    const int r0   = lane >> 2;
    const int c2   = (lane & 3) * 2;
    const int l7   = lane & 7;
    const int l8   = lane & 8;
    const int l16h = (lane & 16) >> 1;

    const int ldr = tid >> 2;
    const int ldc = tid & 3;
    const uint32_t so_base = su + ldr * 80 + ldc * 16;

    float acc[2][8][4];
#pragma unroll
    for (int i = 0; i < 2; i++)
#pragma unroll
        for (int j = 0; j < 8; j++)
#pragma unroll
            for (int k = 0; k < 4; k++) acc[i][j][k] = 0.0f;

    auto issue = [&](int stage, int k0) {
#pragma unroll
        for (int i = 0; i < 2; i++) {
            const int r = ldr + i * 64;
            const uint32_t so = so_base + (uint32_t)stage * G16_STG + i * 64 * 80;
            cpasync16(so + G16_A, Ah + (size_t)(m0 + r) * DD + k0 + ldc * 8);
            cpasync16(so + G16_B, Bh + (size_t)(n0g + r) * DD + k0 + ldc * 8);
        }
        CP_COMMIT();
    };

    issue(0, 0);
    issue(1, 32);

    int stage = 0;
    for (int kt = 0; kt < 32; kt++) {
        CP_WAIT1();
        __syncthreads();
        if (kt < 30) issue((stage + 2) % 3, (kt + 2) * 32);

        const uint32_t sb = su + (uint32_t)stage * G16_STG;
#pragma unroll
        for (int ks = 0; ks < 2; ks++) {
            const int kb = ks * 16;
            uint32_t a[2][4];
#pragma unroll
            for (int mt = 0; mt < 2; mt++) {
                const int row = wm * 32 + mt * 16 + l8 + l7;
                ldsm4(a[mt], sb + row * 80 + (kb + l16h) * 2 + G16_A);
            }
#pragma unroll
            for (int ntp = 0; ntp < 4; ntp++) {
                const int row = wn * 64 + ntp * 16 + l16h + l7;
                uint32_t bfr[4];
                ldsm4(bfr, sb + row * 80 + (kb + l8) * 2 + G16_B);
#pragma unroll
                for (int par = 0; par < 2; par++) {
                    uint32_t pb[2] = {bfr[par * 2], bfr[par * 2 + 1]};
#pragma unroll
                    for (int mt = 0; mt < 2; mt++)
                        mma16816h(acc[mt][ntp * 2 + par], a[mt], pb);
                }
            }
        }
        stage = (stage + 1) % 3;
    }

    const float scale = (seg == 0) ? QSCALE : 1.0f;
    const float* bias = (seg == 0) ? bq : (seg == 1) ? bk : bv;
    __half* Ch = (seg == 0) ? Qo : (seg == 1) ? Ko : Vo;

#pragma unroll
    for (int mt = 0; mt < 2; mt++) {
        const int row = m0 + wm * 32 + mt * 16 + r0;
#pragma unroll
        for (int nt = 0; nt < 8; nt++) {
            const int col = n0 + wn * 64 + nt * 8 + c2;
            const float2 bvv = *(const float2*)(bias + col);
            float v0 = (acc[mt][nt][0] + bvv.x) * scale;
            float v1 = (acc[mt][nt][1] + bvv.y) * scale;
            float v2 = (acc[mt][nt][2] + bvv.x) * scale;
            float v3 = (acc[mt][nt][3] + bvv.y) * scale;
            *(uint32_t*)(Ch + (size_t)row * DD + col)       = pack_f16(v0, v1);
            *(uint32_t*)(Ch + (size_t)(row + 8) * DD + col) = pack_f16(v2, v3);
        }
    }
}

// ---------------------------------------------------------------------------
// Wo GEMM: fp16 A x (fp16 Whi + fp16 Wlo), fp32 acc, 2-stage.
// R11 change: warp grid 2m x 4n (warp tile 64x32) — 20% less smem read
// traffic (A 4x redundancy, B 2x) and ~110 regs -> scheduling headroom.
// ---------------------------------------------------------------------------
#define WO_A    0
#define WO_BH   10240
#define WO_BL   20480
#define WO_STG  30720
#define WO_SMEM (2*WO_STG)

__global__ void __launch_bounds__(256, 2) hmma_wo_kernel(
    const __half* __restrict__ Ah,
    const __half* __restrict__ Bhi, const __half* __restrict__ Blo,
    const float* __restrict__ bias, float* __restrict__ Cf) {
    extern __shared__ char dsm[];
    const uint32_t su = smem_u32(dsm);

    const int tid  = threadIdx.x;
    const int lane = tid & 31;
    const int wid  = tid >> 5;
    const int wm   = wid >> 2;      // 0..1  (64 m-rows each)
    const int wn   = wid & 3;       // 0..3  (32 n-cols each)
    const int m0   = blockIdx.y * 128;
    const int n0   = blockIdx.x * 128;
    const int r0   = lane >> 2;
    const int c2   = (lane & 3) * 2;
    const int l7   = lane & 7;
    const int l8   = lane & 8;
    const int l16h = (lane & 16) >> 1;

    const int ldr = tid >> 2;
    const int ldc = tid & 3;
    const uint32_t so_base = su + ldr * 80 + ldc * 16;

    float acc[4][4][4];   // [mt][nt][4]
#pragma unroll
    for (int i = 0; i < 4; i++)
#pragma unroll
        for (int j = 0; j < 4; j++)
#pragma unroll
            for (int k = 0; k < 4; k++) acc[i][j][k] = 0.0f;

    auto issue = [&](int stage, int k0) {
#pragma unroll
        for (int i = 0; i < 2; i++) {
            const int r = ldr + i * 64;
            const uint32_t so = so_base + (uint32_t)stage * WO_STG + i * 64 * 80;
            cpasync16(so + WO_A,  Ah  + (size_t)(m0 + r) * DD + k0 + ldc * 8);
            cpasync16(so + WO_BH, Bhi + (size_t)(n0 + r) * DD + k0 + ldc * 8);
            cpasync16(so + WO_BL, Blo + (size_t)(n0 + r) * DD + k0 + ldc * 8);
        }
        CP_COMMIT();
    };

    issue(0, 0);

    for (int kt = 0; kt < 32; kt++) {
        CP_WAIT0();
        __syncthreads();
        if (kt < 31) issue((kt + 1) & 1, (kt + 1) * 32);

        const uint32_t sb = su + (uint32_t)(kt & 1) * WO_STG;
#pragma unroll
        for (int ks = 0; ks < 2; ks++) {
            const int kb = ks * 16;
            uint32_t a[4][4];
#pragma unroll
            for (int mt = 0; mt < 4; mt++) {
                const int row = wm * 64 + mt * 16 + l8 + l7;
                ldsm4(a[mt], sb + row * 80 + (kb + l16h) * 2 + WO_A);
            }
#pragma unroll
            for (int ntp = 0; ntp < 2; ntp++) {
                const int row = wn * 32 + ntp * 16 + l16h + l7;
                const uint32_t bo = sb + row * 80 + (kb + l8) * 2;
                uint32_t bh[4], bl[4];
                ldsm4(bh, bo + WO_BH);
                ldsm4(bl, bo + WO_BL);
#pragma unroll
                for (int par = 0; par < 2; par++) {
                    const int nt = ntp * 2 + par;
                    uint32_t ph[2] = {bh[par * 2], bh[par * 2 + 1]};
                    uint32_t pl[2] = {bl[par * 2], bl[par * 2 + 1]};
#pragma unroll
                    for (int mt = 0; mt < 4; mt++) {
                        mma16816h(acc[mt][nt], a[mt], ph);
                        mma16816h(acc[mt][nt], a[mt], pl);
                    }
                }
            }
        }
    }

#pragma unroll
    for (int mt = 0; mt < 4; mt++) {
        const int row = m0 + wm * 64 + mt * 16 + r0;
#pragma unroll
        for (int nt = 0; nt < 4; nt++) {
            const int col = n0 + wn * 32 + nt * 8 + c2;
            const float2 bv = *(const float2*)(bias + col);
            *(float2*)(Cf + (size_t)row * DD + col) =
                make_float2(acc[mt][nt][0] + bv.x, acc[mt][nt][1] + bv.y);
            *(float2*)(Cf + (size_t)(row + 8) * DD + col) =
                make_float2(acc[mt][nt][2] + bv.x, acc[mt][nt][3] + bv.y);
        }
    }
}

// ---------------------------------------------------------------------------
// Attention (R8 numerics) + Wo transpose-split aux CTAs.
// R11 change: __launch_bounds__(256, 2) -> force 2 CTAs/SM (smem 2x36.9KB ok).
// ---------------------------------------------------------------------------
#define LDW   72
#define AKB   (64*LDW*2)
#define ASTG  (2*AKB)
#define ASMEM (2*ASTG)

__global__ void __launch_bounds__(256, 2) attn_tc_kernel(
    const __half* __restrict__ Qh, const __half* __restrict__ Kh,
    const __half* __restrict__ Vh,
    const uint32_t* __restrict__ mbits,
    __half* __restrict__ Co,
    const float* __restrict__ Wo,
    __half* __restrict__ Wohi, __half* __restrict__ Wolo) {
    extern __shared__ char dsm[];
    const int tid  = threadIdx.x;

    // ---- aux: Wo transpose + fp16 hi/lo split (64 CTAs x 16 tiles) ----
    if (blockIdx.x == 16) {
        float* tile = (float*)dsm;  // 32x33
        const int id = blockIdx.y * 4 + blockIdx.z;
        const int tx = tid & 31, j0 = tid >> 5;
        for (int t = id * 16; t < id * 16 + 16; t++) {
            const int n0 = (t & 31) * 32, k0 = (t >> 5) * 32;
            __syncthreads();
            for (int j = j0; j < 32; j += 8)
                tile[j * 33 + tx] = Wo[(size_t)(k0 + j) * DD + n0 + tx];
            __syncthreads();
            for (int j = j0; j < 32; j += 8) {
                float v = tile[tx * 33 + j];
                __half hh = __float2half(v);
                size_t o = (size_t)(n0 + j) * DD + k0 + tx;
                Wohi[o] = hh;
                Wolo[o] = __float2half(v - __half2float(hh));
            }
        }
        return;
    }

    const uint32_t su = smem_u32(dsm);
    const int w    = tid >> 5;
    const int lane = tid & 31;
    const int r0   = lane >> 2;
    const int c2   = (lane & 3) * 2;
    const int l7   = lane & 7;
    const int l8   = lane & 8;
    const int l16h = (lane & 16) >> 1;
    const int b    = blockIdx.z;
    const int h    = blockIdx.y;
    const int q0   = blockIdx.x * 128;

    const int rowA = q0 + w * 16 + r0;
    const int rowB = rowA + 8;
    const size_t headoff = (size_t)h * HD;

    // ---- stage Q, read fragments ----
    {
        const __half* gq = Qh + ((size_t)(b * SS + q0)) * DD + headoff;
#pragma unroll
        for (int it = 0; it < 4; it++) {
            const int idx = it * 256 + tid;
            const int r = idx >> 3, c = idx & 7;
            *(uint4*)(dsm + r * (LDW * 2) + c * 16) =
                *(const uint4*)(gq + (size_t)r * DD + c * 8);
        }
    }
    __syncthreads();
    uint32_t qf[4][4];
#pragma unroll
    for (int ks = 0; ks < 4; ks++) {
        const int row = w * 16 + l8 + l7;
        ldsm4(qf[ks], su + row * (LDW * 2) + (ks * 16 + l16h) * 2);
    }
    __syncthreads();

    const int ldr = tid >> 3;
    const int ldc = tid & 7;
    const size_t gKbase = ((size_t)(b * SS)) * DD + headoff + (size_t)ldr * DD + ldc * 8;
    const uint32_t sKoff = su + ldr * (LDW * 2) + ldc * 16;

    auto issue = [&](int stage, int kc) {
        const size_t g = gKbase + (size_t)kc * DD;
        const uint32_t s = sKoff + (uint32_t)stage * ASTG;
#pragma unroll
        for (int it = 0; it < 2; it++) {
            cpasync16(s + it * 32 * (LDW * 2),       Kh + g + (size_t)it * 32 * DD);
            cpasync16(s + it * 32 * (LDW * 2) + AKB, Vh + g + (size_t)it * 32 * DD);
        }
        CP_COMMIT();
    };

    float accO[8][4];
#pragma unroll
    for (int i = 0; i < 8; i++)
#pragma unroll
        for (int j = 0; j < 4; j++) accO[i][j] = 0.0f;
    float lA = 0.0f, lB = 0.0f;

    const uint32_t* mbA = mbits + (size_t)(b * SS + rowA) * (SS / 32);
    const uint32_t* mbB = mbits + (size_t)(b * SS + rowB) * (SS / 32);

    issue(0, 0);

    for (int ci = 0; ci < 32; ci++) {
        const int kc = ci * 64;
        const uint32_t w0 = mbA[ci * 2], w1 = mbA[ci * 2 + 1];
        const uint32_t w2 = mbB[ci * 2], w3 = mbB[ci * 2 + 1];

        if (ci < 31) { issue((ci + 1) & 1, kc + 64); CP_WAIT1(); }
        else         { CP_WAIT0(); }
        __syncthreads();

        const uint32_t uK = su + (uint32_t)(ci & 1) * ASTG;
        const uint32_t uV = uK + AKB;

        // ---- S = Q.K^T (fp16 in, fp32 acc) ----
        float S[8][4];
#pragma unroll
        for (int i = 0; i < 8; i++)
#pragma unroll
            for (int j = 0; j < 4; j++) S[i][j] = 0.0f;
#pragma unroll
        for (int ks = 0; ks < 4; ks++) {
#pragma unroll
            for (int ntp = 0; ntp < 4; ntp++) {
                const int row = ntp * 16 + l16h + l7;
                uint32_t bfr[4];
                ldsm4(bfr, uK + row * (LDW * 2) + (ks * 16 + l8) * 2);
                uint32_t p0[2] = {bfr[0], bfr[1]};
                uint32_t p1[2] = {bfr[2], bfr[3]};
                mma16816h(S[ntp * 2],     qf[ks], p0);
                mma16816h(S[ntp * 2 + 1], qf[ks], p1);
            }
        }

        // ---- p = mask ? exp2(S) : 0 (M=0 fixed); fp32 l ----
        uint32_t phi[8][2];
#pragma unroll
        for (int nt = 0; nt < 8; nt++) {
            const int p = nt * 8 + c2;
            const uint32_t wa = (p < 32) ? w0 : w1;
            const uint32_t wb = (p < 32) ? w2 : w3;
            const int sh = p & 31;
            float p0 = ((wa >> sh) & 1)       ? fast_exp2(S[nt][0]) : 0.0f;
            float p1 = ((wa >> (sh + 1)) & 1) ? fast_exp2(S[nt][1]) : 0.0f;
            float p2 = ((wb >> sh) & 1)       ? fast_exp2(S[nt][2]) : 0.0f;
            float p3 = ((wb >> (sh + 1)) & 1) ? fast_exp2(S[nt][3]) : 0.0f;
            lA += p0 + p1;
            lB += p2 + p3;
            phi[nt][0] = pack_f16(p0, p1);
            phi[nt][1] = pack_f16(p2, p3);
        }

        // ---- O += P.V (fp16 in, fp32 acc) ----
#pragma unroll
        for (int ks = 0; ks < 4; ks++) {
            uint32_t aP[4] = {phi[2*ks][0], phi[2*ks][1], phi[2*ks+1][0], phi[2*ks+1][1]};
#pragma unroll
            for (int ntp = 0; ntp < 4; ntp++) {
                const int vrow = ks * 16 + l8 + l7;
                const int vcol = ntp * 16 + l16h;
                uint32_t bvv[4];
                ldsm4t(bvv, uV + vrow * (LDW * 2) + vcol * 2);
                uint32_t b0[2] = {bvv[0], bvv[1]};
                uint32_t b1[2] = {bvv[2], bvv[3]};
                mma16816h(accO[2*ntp],     aP, b0);
                mma16816h(accO[2*ntp + 1], aP, b1);
            }
        }
        __syncthreads();
    }

    // ---- final l reduction, normalize, fp16 store ----
    lA += __shfl_xor_sync(0xffffffff, lA, 1);
    lA += __shfl_xor_sync(0xffffffff, lA, 2);
    lB += __shfl_xor_sync(0xffffffff, lB, 1);
    lB += __shfl_xor_sync(0xffffffff, lB, 2);
    const float invA = (lA > 0.0f) ? (1.0f / lA) : 0.0f;
    const float invB = (lB > 0.0f) ? (1.0f / lB) : 0.0f;
    const size_t oA = ((size_t)(b * SS + rowA)) * DD + headoff;
    const size_t oB = ((size_t)(b * SS + rowB)) * DD + headoff;
#pragma unroll
    for (int nt = 0; nt < 8; nt++) {
        const int d = nt * 8 + c2;
        *(uint32_t*)(Co + oA + d) = pack_f16(accO[nt][0] * invA, accO[nt][1] * invA);
        *(uint32_t*)(Co + oB + d) = pack_f16(accO[nt][2] * invB, accO[nt][3] * invB);
    }
}

// ---------------------------------------------------------------------------
extern "C" void kernel_launch(void* const* d_in, const int* in_sizes, int n_in,
                              void* d_out, int out_size) {
    const float* x    = (const float*)d_in[0];
    const int*   mask = (const int*)  d_in[1];
    const float* Wq   = (const float*)d_in[2];
    const float* bq   = (const float*)d_in[3];
    const float* Wk   = (const float*)d_in[4];
    const float* bk   = (const float*)d_in[5];
    const float* Wv   = (const float*)d_in[6];
    const float* bv   = (const float*)d_in[7];
    const float* Wo   = (const float*)d_in[8];
    const float* bo   = (const float*)d_in[9];
    float* out = (float*)d_out;

    __half *xh, *qh, *kh, *vh, *ch, *wt16, *wohi, *wolo;
    uint32_t* mbits;
    cudaGetSymbolAddress((void**)&xh,   g_xh);
    cudaGetSymbolAddress((void**)&qh,   g_qh);
    cudaGetSymbolAddress((void**)&kh,   g_kh);
    cudaGetSymbolAddress((void**)&vh,   g_vh);
    cudaGetSymbolAddress((void**)&ch,   g_ch);
    cudaGetSymbolAddress((void**)&wt16, g_wt16);
    cudaGetSymbolAddress((void**)&wohi, g_wohi);
    cudaGetSymbolAddress((void**)&wolo, g_wolo);
    cudaGetSymbolAddress((void**)&mbits, g_mbits);

    cudaFuncSetAttribute(hmma_qkv_kernel,
                         cudaFuncAttributeMaxDynamicSharedMemorySize, G16_SMEM);
    cudaFuncSetAttribute(hmma_wo_kernel,
                         cudaFuncAttributeMaxDynamicSharedMemorySize, WO_SMEM);
    cudaFuncSetAttribute(attn_tc_kernel,
                         cudaFuncAttributeMaxDynamicSharedMemorySize, ASMEM);

    // prep: x->fp16 + W{q,k,v} transposes (one launch)
    prep_kernel<<<512 + 3072, 256>>>((const float4*)x, xh, Wq, Wk, Wv, wt16);

    // QKV GEMM + mask_pack aux CTAs
    dim3 qkvgrid(25, MROWS / 128);
    hmma_qkv_kernel<<<qkvgrid, 256, G16_SMEM>>>(xh, wt16, bq, bk, bv,
                                                qh, kh, vh, mask, mbits);

    // attention + Wo transpose-split aux CTAs
    dim3 agrid(SS / 128 + 1, HH, BB);   // (17,16,4)
    attn_tc_kernel<<<agrid, 256, ASMEM>>>(qh, kh, vh, mbits, ch, Wo, wohi, wolo);

    // output projection
    dim3 ggrid(DD / 128, MROWS / 128);
    hmma_wo_kernel<<<ggrid, 256, WO_SMEM>>>(ch, wohi, wolo, bo, out);
}

// round 13
// speedup vs baseline: 1.1089x; 1.1089x over previous
#include <cuda_runtime.h>
#include <cuda_bf16.h>
#include <cuda_fp16.h>
#include <cstdint>

#define BB 4
#define SS 2048
#define DD 1024
#define HH 16
#define HD 64
#define MROWS (BB*SS)   // 8192
#define QSCALE 0.18033688011112042f   // 0.125 * log2(e)

// ------------------------- device scratch ----------------------------------
__device__ __half g_xh [MROWS*DD];
__device__ __half g_qh [MROWS*DD];
__device__ __half g_kh [MROWS*DD];
__device__ __half g_vh [MROWS*DD];
__device__ __half g_ch [MROWS*DD];
__device__ __half g_wt16[3*DD*DD];          // Wq^T | Wk^T | Wv^T fp16
__device__ __half g_woh [DD*DD];            // Wo^T fp16 (single precision pass)
__device__ uint32_t g_mbits[BB*SS*(SS/32)];

// ------------------------- helpers -----------------------------------------
__device__ __forceinline__ uint32_t smem_u32(const void* p) {
    uint32_t a;
    asm("{ .reg .u64 t; cvta.to.shared.u64 t, %1; cvt.u32.u64 %0, t; }"
        : "=r"(a) : "l"(p));
    return a;
}
__device__ __forceinline__ float fast_exp2(float x) {
    float r;
    asm("ex2.approx.ftz.f32 %0, %1;" : "=f"(r) : "f"(x));
    return r;
}
__device__ __forceinline__ uint32_t pack_f16(float lo, float hi) {
    uint32_t r;
    asm("cvt.rn.f16x2.f32 %0, %1, %2;" : "=r"(r) : "f"(hi), "f"(lo));
    return r;
}
__device__ __forceinline__ void mma16816h(float* d, const uint32_t* a,
                                          const uint32_t* b) {
    asm volatile(
        "mma.sync.aligned.m16n8k16.row.col.f32.f16.f16.f32 "
        "{%0,%1,%2,%3}, {%4,%5,%6,%7}, {%8,%9}, {%0,%1,%2,%3};"
        : "+f"(d[0]), "+f"(d[1]), "+f"(d[2]), "+f"(d[3])
        : "r"(a[0]), "r"(a[1]), "r"(a[2]), "r"(a[3]), "r"(b[0]), "r"(b[1]));
}
__device__ __forceinline__ void ldsm4(uint32_t* r, uint32_t addr) {
    asm volatile("ldmatrix.sync.aligned.m8n8.x4.shared.b16 {%0,%1,%2,%3}, [%4];"
                 : "=r"(r[0]), "=r"(r[1]), "=r"(r[2]), "=r"(r[3]) : "r"(addr));
}
__device__ __forceinline__ void ldsm4t(uint32_t* r, uint32_t addr) {
    asm volatile("ldmatrix.sync.aligned.m8n8.x4.trans.shared.b16 {%0,%1,%2,%3}, [%4];"
                 : "=r"(r[0]), "=r"(r[1]), "=r"(r[2]), "=r"(r[3]) : "r"(addr));
}
__device__ __forceinline__ void cpasync16(uint32_t saddr, const void* gaddr) {
    asm volatile("cp.async.cg.shared.global [%0], [%1], 16;"
                 :: "r"(saddr), "l"(gaddr));
}
#define CP_COMMIT() asm volatile("cp.async.commit_group;" ::: "memory")
#define CP_WAIT0()  asm volatile("cp.async.wait_group 0;" ::: "memory")
#define CP_WAIT1()  asm volatile("cp.async.wait_group 1;" ::: "memory")

// ---------------------------------------------------------------------------
// prep: tofp16(x) + transpose16(Wq,Wk,Wv) in one launch
// ---------------------------------------------------------------------------
__global__ void __launch_bounds__(256) prep_kernel(
    const float4* __restrict__ x4, __half* __restrict__ xh,
    const float* __restrict__ W0, const float* __restrict__ W1,
    const float* __restrict__ W2, __half* __restrict__ T) {
    const int b = blockIdx.x;
    const int tid = threadIdx.x;
    if (b < 512) {
        const int n4 = MROWS * DD / 4;
        for (int i = b * 256 + tid; i < n4; i += 512 * 256) {
            float4 v = x4[i];
            uint2 o;
            o.x = pack_f16(v.x, v.y);
            o.y = pack_f16(v.z, v.w);
            *(uint2*)(xh + 4 * (size_t)i) = o;
        }
    } else {
        __shared__ float tile[32 * 33];
        const int t = b - 512;              // 0..3071
        const int z = t >> 10, rem = t & 1023;
        const float* W = (z == 0) ? W0 : (z == 1) ? W1 : W2;
        __half* Tz = T + (size_t)z * DD * DD;
        const int n0 = (rem & 31) * 32, k0 = (rem >> 5) * 32;
        const int tx = tid & 31, j0 = tid >> 5;
        for (int j = j0; j < 32; j += 8)
            tile[j * 33 + tx] = W[(size_t)(k0 + j) * DD + n0 + tx];
        __syncthreads();
        for (int j = j0; j < 32; j += 8)
            Tz[(size_t)(n0 + j) * DD + k0 + tx] = __float2half(tile[tx * 33 + j]);
    }
}

// ---------------------------------------------------------------------------
// fused QKV GEMM (fp32-acc) + mask_pack aux CTAs. (unchanged)
// ---------------------------------------------------------------------------
#define G16_A   0
#define G16_B   10240
#define G16_STG 20480
#define G16_SMEM (3*G16_STG)

__global__ void __launch_bounds__(256, 2) hmma_qkv_kernel(
    const __half* __restrict__ Ah, const __half* __restrict__ Bh,
    const float* __restrict__ bq, const float* __restrict__ bk,
    const float* __restrict__ bv,
    __half* __restrict__ Qo, __half* __restrict__ Ko, __half* __restrict__ Vo,
    const int* __restrict__ Mask, uint32_t* __restrict__ Mbits) {
    extern __shared__ char dsm[];
    const int tid  = threadIdx.x;
    const int lane = tid & 31;
    const int wid  = tid >> 5;

    // ---- aux: mask pack ----
    if (blockIdx.x == 24) {
        const int wbase = blockIdx.y * 8192 + wid * 1024;
        for (int it = 0; it < 64; it++) {
            const int w0 = wbase + it * 16;
            int vv[16];
#pragma unroll
            for (int j = 0; j < 16; j++)
                vv[j] = Mask[(size_t)(w0 + j) * 32 + lane];
            uint32_t bb[16];
#pragma unroll
            for (int j = 0; j < 16; j++)
                bb[j] = __ballot_sync(0xffffffff, vv[j] != 0);
            if (lane < 4)
                *(uint4*)(Mbits + w0 + lane * 4) =
                    make_uint4(bb[lane * 4], bb[lane * 4 + 1],
                               bb[lane * 4 + 2], bb[lane * 4 + 3]);
        }
        return;
    }

    const uint32_t su = smem_u32(dsm);
    const int wm   = wid & 3;
    const int wn   = wid >> 2;
    const int m0   = blockIdx.y * 128;
    const int n0g  = blockIdx.x * 128;
    const int seg  = n0g >> 10;
    const int n0   = n0g & 1023;
    const int r0   = lane >> 2;
    const int c2   = (lane & 3) * 2;
    const int l7   = lane & 7;
    const int l8   = lane & 8;
    const int l16h = (lane & 16) >> 1;

    const int ldr = tid >> 2;
    const int ldc = tid & 3;
    const uint32_t so_base = su + ldr * 80 + ldc * 16;

    float acc[2][8][4];
#pragma unroll
    for (int i = 0; i < 2; i++)
#pragma unroll
        for (int j = 0; j < 8; j++)
#pragma unroll
            for (int k = 0; k < 4; k++) acc[i][j][k] = 0.0f;

    auto issue = [&](int stage, int k0) {
#pragma unroll
        for (int i = 0; i < 2; i++) {
            const int r = ldr + i * 64;
            const uint32_t so = so_base + (uint32_t)stage * G16_STG + i * 64 * 80;
            cpasync16(so + G16_A, Ah + (size_t)(m0 + r) * DD + k0 + ldc * 8);
            cpasync16(so + G16_B, Bh + (size_t)(n0g + r) * DD + k0 + ldc * 8);
        }
        CP_COMMIT();
    };

    issue(0, 0);
    issue(1, 32);

    int stage = 0;
    for (int kt = 0; kt < 32; kt++) {
        CP_WAIT1();
        __syncthreads();
        if (kt < 30) issue((stage + 2) % 3, (kt + 2) * 32);

        const uint32_t sb = su + (uint32_t)stage * G16_STG;
#pragma unroll
        for (int ks = 0; ks < 2; ks++) {
            const int kb = ks * 16;
            uint32_t a[2][4];
#pragma unroll
            for (int mt = 0; mt < 2; mt++) {
                const int row = wm * 32 + mt * 16 + l8 + l7;
                ldsm4(a[mt], sb + row * 80 + (kb + l16h) * 2 + G16_A);
            }
#pragma unroll
            for (int ntp = 0; ntp < 4; ntp++) {
                const int row = wn * 64 + ntp * 16 + l16h + l7;
                uint32_t bfr[4];
                ldsm4(bfr, sb + row * 80 + (kb + l8) * 2 + G16_B);
#pragma unroll
                for (int par = 0; par < 2; par++) {
                    uint32_t pb[2] = {bfr[par * 2], bfr[par * 2 + 1]};
#pragma unroll
                    for (int mt = 0; mt < 2; mt++)
                        mma16816h(acc[mt][ntp * 2 + par], a[mt], pb);
                }
            }
        }
        stage = (stage + 1) % 3;
    }

    const float scale = (seg == 0) ? QSCALE : 1.0f;
    const float* bias = (seg == 0) ? bq : (seg == 1) ? bk : bv;
    __half* Ch = (seg == 0) ? Qo : (seg == 1) ? Ko : Vo;

#pragma unroll
    for (int mt = 0; mt < 2; mt++) {
        const int row = m0 + wm * 32 + mt * 16 + r0;
#pragma unroll
        for (int nt = 0; nt < 8; nt++) {
            const int col = n0 + wn * 64 + nt * 8 + c2;
            const float2 bvv = *(const float2*)(bias + col);
            float v0 = (acc[mt][nt][0] + bvv.x) * scale;
            float v1 = (acc[mt][nt][1] + bvv.y) * scale;
            float v2 = (acc[mt][nt][2] + bvv.x) * scale;
            float v3 = (acc[mt][nt][3] + bvv.y) * scale;
            *(uint32_t*)(Ch + (size_t)row * DD + col)       = pack_f16(v0, v1);
            *(uint32_t*)(Ch + (size_t)(row + 8) * DD + col) = pack_f16(v2, v3);
        }
    }
}

// ---------------------------------------------------------------------------
// Wo GEMM: fp16 A x fp16 W (SINGLE pass), fp32 acc, 2-stage cp.async.
// 4m x 2n warp grid (R10 layout).
// ---------------------------------------------------------------------------
#define WO_A    0
#define WO_B    10240
#define WO_STG  20480
#define WO_SMEM (2*WO_STG)

__global__ void __launch_bounds__(256, 2) hmma_wo_kernel(
    const __half* __restrict__ Ah, const __half* __restrict__ Bh,
    const float* __restrict__ bias, float* __restrict__ Cf) {
    extern __shared__ char dsm[];
    const uint32_t su = smem_u32(dsm);

    const int tid  = threadIdx.x;
    const int lane = tid & 31;
    const int wid  = tid >> 5;
    const int wm   = wid & 3;
    const int wn   = wid >> 2;
    const int m0   = blockIdx.y * 128;
    const int n0   = blockIdx.x * 128;
    const int r0   = lane >> 2;
    const int c2   = (lane & 3) * 2;
    const int l7   = lane & 7;
    const int l8   = lane & 8;
    const int l16h = (lane & 16) >> 1;

    const int ldr = tid >> 2;
    const int ldc = tid & 3;
    const uint32_t so_base = su + ldr * 80 + ldc * 16;

    float acc[2][8][4];
#pragma unroll
    for (int i = 0; i < 2; i++)
#pragma unroll
        for (int j = 0; j < 8; j++)
#pragma unroll
            for (int k = 0; k < 4; k++) acc[i][j][k] = 0.0f;

    auto issue = [&](int stage, int k0) {
#pragma unroll
        for (int i = 0; i < 2; i++) {
            const int r = ldr + i * 64;
            const uint32_t so = so_base + (uint32_t)stage * WO_STG + i * 64 * 80;
            cpasync16(so + WO_A, Ah + (size_t)(m0 + r) * DD + k0 + ldc * 8);
            cpasync16(so + WO_B, Bh + (size_t)(n0 + r) * DD + k0 + ldc * 8);
        }
        CP_COMMIT();
    };

    issue(0, 0);

    for (int kt = 0; kt < 32; kt++) {
        CP_WAIT0();
        __syncthreads();
        if (kt < 31) issue((kt + 1) & 1, (kt + 1) * 32);

        const uint32_t sb = su + (uint32_t)(kt & 1) * WO_STG;
#pragma unroll
        for (int ks = 0; ks < 2; ks++) {
            const int kb = ks * 16;
            uint32_t a[2][4];
#pragma unroll
            for (int mt = 0; mt < 2; mt++) {
                const int row = wm * 32 + mt * 16 + l8 + l7;
                ldsm4(a[mt], sb + row * 80 + (kb + l16h) * 2 + WO_A);
            }
#pragma unroll
            for (int ntp = 0; ntp < 4; ntp++) {
                const int row = wn * 64 + ntp * 16 + l16h + l7;
                uint32_t bfr[4];
                ldsm4(bfr, sb + row * 80 + (kb + l8) * 2 + WO_B);
#pragma unroll
                for (int par = 0; par < 2; par++) {
                    uint32_t pb[2] = {bfr[par * 2], bfr[par * 2 + 1]};
#pragma unroll
                    for (int mt = 0; mt < 2; mt++)
                        mma16816h(acc[mt][ntp * 2 + par], a[mt], pb);
                }
            }
        }
    }

#pragma unroll
    for (int mt = 0; mt < 2; mt++) {
        const int row = m0 + wm * 32 + mt * 16 + r0;
#pragma unroll
        for (int nt = 0; nt < 8; nt++) {
            const int col = n0 + wn * 64 + nt * 8 + c2;
            const float2 bv = *(const float2*)(bias + col);
            *(float2*)(Cf + (size_t)row * DD + col) =
                make_float2(acc[mt][nt][0] + bv.x, acc[mt][nt][1] + bv.y);
            *(float2*)(Cf + (size_t)(row + 8) * DD + col) =
                make_float2(acc[mt][nt][2] + bv.x, acc[mt][nt][3] + bv.y);
        }
    }
}

// ---------------------------------------------------------------------------
// Attention (R8/R10 numerics) + Wo transpose aux CTAs (fp16 single).
// launch_bounds(256) — R11's (256,2) reverted (it regressed ~10us).
// ---------------------------------------------------------------------------
#define LDW   72
#define AKB   (64*LDW*2)
#define ASTG  (2*AKB)
#define ASMEM (2*ASTG)

__global__ void __launch_bounds__(256) attn_tc_kernel(
    const __half* __restrict__ Qh, const __half* __restrict__ Kh,
    const __half* __restrict__ Vh,
    const uint32_t* __restrict__ mbits,
    __half* __restrict__ Co,
    const float* __restrict__ Wo, __half* __restrict__ Woh) {
    extern __shared__ char dsm[];
    const int tid  = threadIdx.x;

    // ---- aux: Wo transpose -> fp16 (64 CTAs x 16 tiles) ----
    if (blockIdx.x == 16) {
        float* tile = (float*)dsm;  // 32x33
        const int id = blockIdx.y * 4 + blockIdx.z;
        const int tx = tid & 31, j0 = tid >> 5;
        for (int t = id * 16; t < id * 16 + 16; t++) {
            const int n0 = (t & 31) * 32, k0 = (t >> 5) * 32;
            __syncthreads();
            for (int j = j0; j < 32; j += 8)
                tile[j * 33 + tx] = Wo[(size_t)(k0 + j) * DD + n0 + tx];
            __syncthreads();
            for (int j = j0; j < 32; j += 8)
                Woh[(size_t)(n0 + j) * DD + k0 + tx] = __float2half(tile[tx * 33 + j]);
        }
        return;
    }

    const uint32_t su = smem_u32(dsm);
    const int w    = tid >> 5;
    const int lane = tid & 31;
    const int r0   = lane >> 2;
    const int c2   = (lane & 3) * 2;
    const int l7   = lane & 7;
    const int l8   = lane & 8;
    const int l16h = (lane & 16) >> 1;
    const int b    = blockIdx.z;
    const int h    = blockIdx.y;
    const int q0   = blockIdx.x * 128;

    const int rowA = q0 + w * 16 + r0;
    const int rowB = rowA + 8;
    const size_t headoff = (size_t)h * HD;

    // ---- stage Q, read fragments ----
    {
        const __half* gq = Qh + ((size_t)(b * SS + q0)) * DD + headoff;
#pragma unroll
        for (int it = 0; it < 4; it++) {
            const int idx = it * 256 + tid;
            const int r = idx >> 3, c = idx & 7;
            *(uint4*)(dsm + r * (LDW * 2) + c * 16) =
                *(const uint4*)(gq + (size_t)r * DD + c * 8);
        }
    }
    __syncthreads();
    uint32_t qf[4][4];
#pragma unroll
    for (int ks = 0; ks < 4; ks++) {
        const int row = w * 16 + l8 + l7;
        ldsm4(qf[ks], su + row * (LDW * 2) + (ks * 16 + l16h) * 2);
    }
    __syncthreads();

    const int ldr = tid >> 3;
    const int ldc = tid & 7;
    const size_t gKbase = ((size_t)(b * SS)) * DD + headoff + (size_t)ldr * DD + ldc * 8;
    const uint32_t sKoff = su + ldr * (LDW * 2) + ldc * 16;

    auto issue = [&](int stage, int kc) {
        const size_t g = gKbase + (size_t)kc * DD;
        const uint32_t s = sKoff + (uint32_t)stage * ASTG;
#pragma unroll
        for (int it = 0; it < 2; it++) {
            cpasync16(s + it * 32 * (LDW * 2),       Kh + g + (size_t)it * 32 * DD);
            cpasync16(s + it * 32 * (LDW * 2) + AKB, Vh + g + (size_t)it * 32 * DD);
        }
        CP_COMMIT();
    };

    float accO[8][4];
#pragma unroll
    for (int i = 0; i < 8; i++)
#pragma unroll
        for (int j = 0; j < 4; j++) accO[i][j] = 0.0f;
    float lA = 0.0f, lB = 0.0f;

    const uint32_t* mbA = mbits + (size_t)(b * SS + rowA) * (SS / 32);
    const uint32_t* mbB = mbits + (size_t)(b * SS + rowB) * (SS / 32);

    issue(0, 0);

    for (int ci = 0; ci < 32; ci++) {
        const int kc = ci * 64;
        const uint32_t w0 = mbA[ci * 2], w1 = mbA[ci * 2 + 1];
        const uint32_t w2 = mbB[ci * 2], w3 = mbB[ci * 2 + 1];

        if (ci < 31) { issue((ci + 1) & 1, kc + 64); CP_WAIT1(); }
        else         { CP_WAIT0(); }
        __syncthreads();

        const uint32_t uK = su + (uint32_t)(ci & 1) * ASTG;
        const uint32_t uV = uK + AKB;

        // ---- S = Q.K^T (fp16 in, fp32 acc) ----
        float S[8][4];
#pragma unroll
        for (int i = 0; i < 8; i++)
#pragma unroll
            for (int j = 0; j < 4; j++) S[i][j] = 0.0f;
#pragma unroll
        for (int ks = 0; ks < 4; ks++) {
#pragma unroll
            for (int ntp = 0; ntp < 4; ntp++) {
                const int row = ntp * 16 + l16h + l7;
                uint32_t bfr[4];
                ldsm4(bfr, uK + row * (LDW * 2) + (ks * 16 + l8) * 2);
                uint32_t p0[2] = {bfr[0], bfr[1]};
                uint32_t p1[2] = {bfr[2], bfr[3]};
                mma16816h(S[ntp * 2],     qf[ks], p0);
                mma16816h(S[ntp * 2 + 1], qf[ks], p1);
            }
        }

        // ---- p = mask ? exp2(S) : 0 (M=0 fixed); fp32 l ----
        uint32_t phi[8][2];
#pragma unroll
        for (int nt = 0; nt < 8; nt++) {
            const int p = nt * 8 + c2;
            const uint32_t wa = (p < 32) ? w0 : w1;
            const uint32_t wb = (p < 32) ? w2 : w3;
            const int sh = p & 31;
            float p0 = ((wa >> sh) & 1)       ? fast_exp2(S[nt][0]) : 0.0f;
            float p1 = ((wa >> (sh + 1)) & 1) ? fast_exp2(S[nt][1]) : 0.0f;
            float p2 = ((wb >> sh) & 1)       ? fast_exp2(S[nt][2]) : 0.0f;
            float p3 = ((wb >> (sh + 1)) & 1) ? fast_exp2(S[nt][3]) : 0.0f;
            lA += p0 + p1;
            lB += p2 + p3;
            phi[nt][0] = pack_f16(p0, p1);
            phi[nt][1] = pack_f16(p2, p3);
        }

        // ---- O += P.V (fp16 in, fp32 acc) ----
#pragma unroll
        for (int ks = 0; ks < 4; ks++) {
            uint32_t aP[4] = {phi[2*ks][0], phi[2*ks][1], phi[2*ks+1][0], phi[2*ks+1][1]};
#pragma unroll
            for (int ntp = 0; ntp < 4; ntp++) {
                const int vrow = ks * 16 + l8 + l7;
                const int vcol = ntp * 16 + l16h;
                uint32_t bvv[4];
                ldsm4t(bvv, uV + vrow * (LDW * 2) + vcol * 2);
                uint32_t b0[2] = {bvv[0], bvv[1]};
                uint32_t b1[2] = {bvv[2], bvv[3]};
                mma16816h(accO[2*ntp],     aP, b0);
                mma16816h(accO[2*ntp + 1], aP, b1);
            }
        }
        __syncthreads();
    }

    // ---- final l reduction, normalize, fp16 store ----
    lA += __shfl_xor_sync(0xffffffff, lA, 1);
    lA += __shfl_xor_sync(0xffffffff, lA, 2);
    lB += __shfl_xor_sync(0xffffffff, lB, 1);
    lB += __shfl_xor_sync(0xffffffff, lB, 2);
    const float invA = (lA > 0.0f) ? (1.0f / lA) : 0.0f;
    const float invB = (lB > 0.0f) ? (1.0f / lB) : 0.0f;
    const size_t oA = ((size_t)(b * SS + rowA)) * DD + headoff;
    const size_t oB = ((size_t)(b * SS + rowB)) * DD + headoff;
#pragma unroll
    for (int nt = 0; nt < 8; nt++) {
        const int d = nt * 8 + c2;
        *(uint32_t*)(Co + oA + d) = pack_f16(accO[nt][0] * invA, accO[nt][1] * invA);
        *(uint32_t*)(Co + oB + d) = pack_f16(accO[nt][2] * invB, accO[nt][3] * invB);
    }
}

// ---------------------------------------------------------------------------
extern "C" void kernel_launch(void* const* d_in, const int* in_sizes, int n_in,
                              void* d_out, int out_size) {
    const float* x    = (const float*)d_in[0];
    const int*   mask = (const int*)  d_in[1];
    const float* Wq   = (const float*)d_in[2];
    const float* bq   = (const float*)d_in[3];
    const float* Wk   = (const float*)d_in[4];
    const float* bk   = (const float*)d_in[5];
    const float* Wv   = (const float*)d_in[6];
    const float* bv   = (const float*)d_in[7];
    const float* Wo   = (const float*)d_in[8];
    const float* bo   = (const float*)d_in[9];
    float* out = (float*)d_out;

    __half *xh, *qh, *kh, *vh, *ch, *wt16, *woh;
    uint32_t* mbits;
    cudaGetSymbolAddress((void**)&xh,   g_xh);
    cudaGetSymbolAddress((void**)&qh,   g_qh);
    cudaGetSymbolAddress((void**)&kh,   g_kh);
    cudaGetSymbolAddress((void**)&vh,   g_vh);
    cudaGetSymbolAddress((void**)&ch,   g_ch);
    cudaGetSymbolAddress((void**)&wt16, g_wt16);
    cudaGetSymbolAddress((void**)&woh,  g_woh);
    cudaGetSymbolAddress((void**)&mbits, g_mbits);

    cudaFuncSetAttribute(hmma_qkv_kernel,
                         cudaFuncAttributeMaxDynamicSharedMemorySize, G16_SMEM);
    cudaFuncSetAttribute(hmma_wo_kernel,
                         cudaFuncAttributeMaxDynamicSharedMemorySize, WO_SMEM);
    cudaFuncSetAttribute(attn_tc_kernel,
                         cudaFuncAttributeMaxDynamicSharedMemorySize, ASMEM);

    // prep: x->fp16 + W{q,k,v} transposes (one launch)
    prep_kernel<<<512 + 3072, 256>>>((const float4*)x, xh, Wq, Wk, Wv, wt16);

    // QKV GEMM + mask_pack aux CTAs
    dim3 qkvgrid(25, MROWS / 128);
    hmma_qkv_kernel<<<qkvgrid, 256, G16_SMEM>>>(xh, wt16, bq, bk, bv,
                                                qh, kh, vh, mask, mbits);

    // attention + Wo transpose aux CTAs
    dim3 agrid(SS / 128 + 1, HH, BB);   // (17,16,4)
    attn_tc_kernel<<<agrid, 256, ASMEM>>>(qh, kh, vh, mbits, ch, Wo, woh);

    // output projection (single-pass fp16 Wo, fp32 acc)
    dim3 ggrid(DD / 128, MROWS / 128);
    hmma_wo_kernel<<<ggrid, 256, WO_SMEM>>>(ch, woh, bo, out);
}